// round 14
// baseline (speedup 1.0000x reference)
#include <cuda_runtime.h>
#include <cuda_bf16.h>
#include <cstdint>

// out[b,s,d] = keep ? (emb[x[b,s],d] + pe[s,d]) * (1/0.9) : 0
// keep from JAX threefry2x32 (partitionable): key=(0,42), ctr=(0,i),
// bits = out0^out1, keep <=> bits < 0xE6666600  (== u<0.9f exactly)

// 2^r multipliers for the IMAD.WIDE rotate trick (opaque via __constant__).
__constant__ uint32_t ROTM[4] = {1u << 13, 1u << 26, 1u << 17, 1u << 16};

#define KS1 42u
#define KS2 0x1BD11BF0u

// Wide round on 4 interleaved chains with x0-side key injection folded into
// the add: IADD3(flex) + IMAD.WIDE(fma) + LOP3(alu)
#define W4C(mm, c01)                                                       \
    _Pragma("unroll") for (int k = 0; k < 4; k++) {                        \
        x0[k] = x0[k] + x1[k] + (c01);                                     \
        unsigned long long p;                                              \
        asm("mul.wide.u32 %0, %1, %2;" : "=l"(p) : "r"(x1[k]), "r"(mm));   \
        x1[k] = ((uint32_t)p | (uint32_t)(p >> 32)) ^ x0[k];               \
    }

// Shift round on 4 interleaved chains: IADD3(flex) + SHF(alu) + LOP3(alu)
#define S4(rr)                                                             \
    _Pragma("unroll") for (int k = 0; k < 4; k++) {                        \
        x0[k] += x1[k];                                                    \
        x1[k] = __funnelshift_l(x1[k], x1[k], (rr)) ^ x0[k];               \
    }

// x1-side key injection
#define INJ4(c1)                                                           \
    _Pragma("unroll") for (int k = 0; k < 4; k++) { x1[k] += (c1); }

__device__ __forceinline__ void tf_bits4(uint32_t ctr, uint32_t m13,
                                         uint32_t m26, uint32_t m17,
                                         uint32_t m16, uint32_t* bits) {
    uint32_t x0[4], x1[4];
    // Round-1 specialization: x0 pre-add is 0, so post-add x0 == x1_init.
#pragma unroll
    for (int k = 0; k < 4; k++) {
        x1[k] = ctr + (KS1 + (uint32_t)k);
        x0[k] = x1[k];
        unsigned long long p;
        asm("mul.wide.u32 %0, %1, %2;" : "=l"(p) : "r"(x1[k]), "r"(m13));
        x1[k] = ((uint32_t)p | (uint32_t)(p >> 32)) ^ x0[k];
    }
    S4(15) W4C(m26, 0u) S4(6)
    INJ4(KS2 + 1u)
    W4C(m17, KS1) S4(29) W4C(m16, 0u) S4(24)      // x0 += ks1 folded
    INJ4(2u)                                       // ks0 == 0
    W4C(m13, KS2) S4(15) W4C(m26, 0u) S4(6)       // x0 += ks2 folded
    INJ4(KS1 + 3u)
    W4C(m17, 0u) S4(29) W4C(m16, 0u) S4(24)       // x0 += ks0 == 0
    INJ4(KS2 + 4u)
    W4C(m13, KS1) S4(15) W4C(m26, 0u) S4(6)       // x0 += ks1 folded
#pragma unroll
    for (int k = 0; k < 4; k++) bits[k] = (x0[k] + KS2) ^ (x1[k] + 5u);
}

// Streaming 128-bit store: output is write-once, never re-read -> evict-first
// keeps L2 capacity for embedding-row reuse.
__device__ __forceinline__ void stg_cs128(float* p, float4 v) {
    asm volatile("st.global.cs.v4.f32 [%0], {%1, %2, %3, %4};"
                 :: "l"(p), "f"(v.x), "f"(v.y), "f"(v.z), "f"(v.w)
                 : "memory");
}

// E = 8 elems/thread: 4 d-values x 2 batches (6.9 waves, 1.4% tail).
// blockIdx.x = s*8 + half*4 + bp   (bp selects batch pair {2bp, 2bp+1})
__global__ __launch_bounds__(128) void embed_pe_drop_kernel(
    const int* __restrict__ x,
    const float* __restrict__ emb,
    float* __restrict__ out)
{
    const uint32_t m13 = ROTM[0], m26 = ROTM[1], m17 = ROTM[2], m16 = ROTM[3];

    const uint32_t bp   = blockIdx.x & 3u;          // batch pair 0..3
    const uint32_t half = (blockIdx.x >> 2) & 1u;   // d half
    const uint32_t s    = blockIdx.x >> 3;          // 0..2047
    const uint32_t d    = (half << 9) + threadIdx.x * 4u;

    // PE once per thread, pre-scaled by 1/0.9.
    const float KNEG   = -0.02595256324130752f;   // -log2(10000)/512
    const float STEP   = 0.98217188542871857f;    // 2^KNEG
    const float INV2PI = 0.15915494309189535f;
    const float TWOPI  = 6.2831853071795865f;
    const float INVKEEP = 1.0f / 0.9f;
    const float sf = (float)s;
    const float w0 = exp2f((float)(d >> 1) * KNEG) * INV2PI;
    const float w1 = w0 * STEP;
    float pe[4];
    {
        float t0 = sf * w0, t1 = sf * w1;
        float a0 = (t0 - rintf(t0)) * TWOPI;
        float a1 = (t1 - rintf(t1)) * TWOPI;
        pe[0] = __sinf(a0) * INVKEEP; pe[1] = __cosf(a0) * INVKEEP;
        pe[2] = __sinf(a1) * INVKEEP; pe[3] = __cosf(a1) * INVKEEP;
    }

    const uint32_t b0 = bp * 2u;
    const uint32_t j0 = (b0 << 21) + (s << 10) + d;   // flat idx, batch b0
    const uint32_t JSTEP = 2048u * 1024u;             // 1 << 21

    // ---- batch b0 ----
    {
        const int tok = __ldg(x + (b0 << 11) + s);
        const float4 e = *reinterpret_cast<const float4*>(
            emb + ((size_t)tok << 10) + d);
        uint32_t bits[4];
        tf_bits4(j0, m13, m26, m17, m16, bits);
        float4 y;
        y.x = (bits[0] < 0xE6666600u) ? fmaf(e.x, INVKEEP, pe[0]) : 0.0f;
        y.y = (bits[1] < 0xE6666600u) ? fmaf(e.y, INVKEEP, pe[1]) : 0.0f;
        y.z = (bits[2] < 0xE6666600u) ? fmaf(e.z, INVKEEP, pe[2]) : 0.0f;
        y.w = (bits[3] < 0xE6666600u) ? fmaf(e.w, INVKEEP, pe[3]) : 0.0f;
        stg_cs128(out + j0, y);
    }

    // ---- batch b0 + 1 ----
    {
        const uint32_t j1 = j0 + JSTEP;
        const int tok = __ldg(x + ((b0 + 1u) << 11) + s);
        const float4 e = *reinterpret_cast<const float4*>(
            emb + ((size_t)tok << 10) + d);
        uint32_t bits[4];
        tf_bits4(j1, m13, m26, m17, m16, bits);
        float4 y;
        y.x = (bits[0] < 0xE6666600u) ? fmaf(e.x, INVKEEP, pe[0]) : 0.0f;
        y.y = (bits[1] < 0xE6666600u) ? fmaf(e.y, INVKEEP, pe[1]) : 0.0f;
        y.z = (bits[2] < 0xE6666600u) ? fmaf(e.z, INVKEEP, pe[2]) : 0.0f;
        y.w = (bits[3] < 0xE6666600u) ? fmaf(e.w, INVKEEP, pe[3]) : 0.0f;
        stg_cs128(out + j1, y);
    }
}

extern "C" void kernel_launch(void* const* d_in, const int* in_sizes, int n_in,
                              void* d_out, int out_size) {
    const int* x;
    const float* emb;
    if (in_sizes[0] == 8 * 2048) {
        x = (const int*)d_in[0];
        emb = (const float*)d_in[1];
    } else {
        x = (const int*)d_in[1];
        emb = (const float*)d_in[0];
    }
    float* out = (float*)d_out;

    // 2048 s * 2 halves * 4 batch-pairs = 16384 blocks
    embed_pe_drop_kernel<<<16384, 128>>>(x, emb, out);
}

// round 15
// speedup vs baseline: 1.0908x; 1.0908x over previous
#include <cuda_runtime.h>
#include <cuda_bf16.h>
#include <cstdint>

// out[b,s,d] = keep ? (emb[x[b,s],d] + pe[s,d]) * (1/0.9) : 0
// keep from JAX threefry2x32 (partitionable): key=(0,42), ctr=(0,i),
// bits = out0^out1, keep <=> bits < 0xE6666600  (== u<0.9f exactly)
//
// All rounds use SHF (funnel shift) rotates: 3 true issue slots per round.
// IMAD.WIDE "fma-pipe" rotates cost 4 slots (dual-reg write) — measured
// slower across R3/R5/R12 despite balancing pipe counters.

#define KS1 42u
#define KS2 0x1BD11BF0u

// Shift round on 4 interleaved chains with x0-side key injection folded in:
//   IADD3(flex) + SHF(alu) + LOP3(alu)
#define S4C(rr, c01)                                                       \
    _Pragma("unroll") for (int k = 0; k < 4; k++) {                        \
        x0[k] = x0[k] + x1[k] + (c01);                                     \
        x1[k] = __funnelshift_l(x1[k], x1[k], (rr)) ^ x0[k];               \
    }

#define S4(rr) S4C(rr, 0u)

// x1-side key injection
#define INJ4(c1)                                                           \
    _Pragma("unroll") for (int k = 0; k < 4; k++) { x1[k] += (c1); }

__device__ __forceinline__ void tf_bits4(uint32_t ctr, uint32_t* bits) {
    uint32_t x0[4], x1[4];
    // Round-1 specialization: x0 pre-add is 0, so post-add x0 == x1_init.
#pragma unroll
    for (int k = 0; k < 4; k++) {
        x1[k] = ctr + (KS1 + (uint32_t)k);
        x0[k] = x1[k];
        x1[k] = __funnelshift_l(x1[k], x1[k], 13) ^ x0[k];
    }
    S4(15) S4(26) S4(6)
    INJ4(KS2 + 1u)
    S4C(17, KS1) S4(29) S4(16) S4(24)      // x0 += ks1 folded
    INJ4(2u)                                // ks0 == 0
    S4C(13, KS2) S4(15) S4(26) S4(6)       // x0 += ks2 folded
    INJ4(KS1 + 3u)
    S4(17) S4(29) S4(16) S4(24)            // x0 += ks0 == 0
    INJ4(KS2 + 4u)
    S4C(13, KS1) S4(15) S4(26) S4(6)       // x0 += ks1 folded
#pragma unroll
    for (int k = 0; k < 4; k++) bits[k] = (x0[k] + KS2) ^ (x1[k] + 5u);
}

// E = 8 elems/thread: 4 d-values x 2 batches (6.9 waves, 1.4% tail).
// blockIdx.x = s*8 + half*4 + bp   (bp selects batch pair {2bp, 2bp+1})
__global__ __launch_bounds__(128) void embed_pe_drop_kernel(
    const int* __restrict__ x,
    const float* __restrict__ emb,
    float* __restrict__ out)
{
    const uint32_t bp   = blockIdx.x & 3u;          // batch pair 0..3
    const uint32_t half = (blockIdx.x >> 2) & 1u;   // d half
    const uint32_t s    = blockIdx.x >> 3;          // 0..2047
    const uint32_t d    = (half << 9) + threadIdx.x * 4u;

    // PE once per thread, pre-scaled by 1/0.9.
    const float KNEG   = -0.02595256324130752f;   // -log2(10000)/512
    const float STEP   = 0.98217188542871857f;    // 2^KNEG
    const float INV2PI = 0.15915494309189535f;
    const float TWOPI  = 6.2831853071795865f;
    const float INVKEEP = 1.0f / 0.9f;
    const float sf = (float)s;
    const float w0 = exp2f((float)(d >> 1) * KNEG) * INV2PI;
    const float w1 = w0 * STEP;
    float pe[4];
    {
        float t0 = sf * w0, t1 = sf * w1;
        float a0 = (t0 - rintf(t0)) * TWOPI;
        float a1 = (t1 - rintf(t1)) * TWOPI;
        pe[0] = __sinf(a0) * INVKEEP; pe[1] = __cosf(a0) * INVKEEP;
        pe[2] = __sinf(a1) * INVKEEP; pe[3] = __cosf(a1) * INVKEEP;
    }

    const uint32_t b0 = bp * 2u;
    const uint32_t j0 = (b0 << 21) + (s << 10) + d;   // flat idx, batch b0
    const uint32_t JSTEP = 2048u * 1024u;             // 1 << 21

    // ---- batch b0 ----
    {
        const int tok = __ldg(x + (b0 << 11) + s);
        const float4 e = *reinterpret_cast<const float4*>(
            emb + ((size_t)tok << 10) + d);
        uint32_t bits[4];
        tf_bits4(j0, bits);
        float4 y;
        y.x = (bits[0] < 0xE6666600u) ? fmaf(e.x, INVKEEP, pe[0]) : 0.0f;
        y.y = (bits[1] < 0xE6666600u) ? fmaf(e.y, INVKEEP, pe[1]) : 0.0f;
        y.z = (bits[2] < 0xE6666600u) ? fmaf(e.z, INVKEEP, pe[2]) : 0.0f;
        y.w = (bits[3] < 0xE6666600u) ? fmaf(e.w, INVKEEP, pe[3]) : 0.0f;
        *reinterpret_cast<float4*>(out + j0) = y;
    }

    // ---- batch b0 + 1 ----
    {
        const uint32_t j1 = j0 + JSTEP;
        const int tok = __ldg(x + ((b0 + 1u) << 11) + s);
        const float4 e = *reinterpret_cast<const float4*>(
            emb + ((size_t)tok << 10) + d);
        uint32_t bits[4];
        tf_bits4(j1, bits);
        float4 y;
        y.x = (bits[0] < 0xE6666600u) ? fmaf(e.x, INVKEEP, pe[0]) : 0.0f;
        y.y = (bits[1] < 0xE6666600u) ? fmaf(e.y, INVKEEP, pe[1]) : 0.0f;
        y.z = (bits[2] < 0xE6666600u) ? fmaf(e.z, INVKEEP, pe[2]) : 0.0f;
        y.w = (bits[3] < 0xE6666600u) ? fmaf(e.w, INVKEEP, pe[3]) : 0.0f;
        *reinterpret_cast<float4*>(out + j1) = y;
    }
}

extern "C" void kernel_launch(void* const* d_in, const int* in_sizes, int n_in,
                              void* d_out, int out_size) {
    const int* x;
    const float* emb;
    if (in_sizes[0] == 8 * 2048) {
        x = (const int*)d_in[0];
        emb = (const float*)d_in[1];
    } else {
        x = (const int*)d_in[1];
        emb = (const float*)d_in[0];
    }
    float* out = (float*)d_out;

    // 2048 s * 2 halves * 4 batch-pairs = 16384 blocks
    embed_pe_drop_kernel<<<16384, 128>>>(x, emb, out);
}